// round 5
// baseline (speedup 1.0000x reference)
#include <cuda_runtime.h>
#include <cuda_bf16.h>
#include <cstdint>

#define BSZ 16
#define SSZ 4096
#define HSZ 1024
#define NTOK (BSZ * SSZ)

#define M_CTA 128
#define N_CHUNK 256
#define NCHUNK (HSZ / N_CHUNK)   // 4
#define BK 32
#define NKSTAGE (HSZ / BK)       // 32 stages per n-chunk
#define NSTAGE 3                 // pipeline depth
#define PITCH 80                 // bytes per 32-elem bf16 row (64B data + 16B skew)

// dynamic smem layout (bytes)
#define SOFF_SCORE 0             // float[128]
#define SOFF_KEY   512           // float[1024]
#define SOFF_BIAS  4608          // float[1024]
#define SOFF_STAGE 8704
#define AHI 0
#define ALO (128 * PITCH)        // 10240
#define BHI (2 * 128 * PITCH)    // 20480
#define BLO (BHI + 256 * PITCH)  // 40960
#define STAGE_BYTES (BLO + 256 * PITCH)            // 61440
#define SMEM_TOTAL (SOFF_STAGE + NSTAGE * STAGE_BYTES)  // 193024

// ---- scratch (no allocations allowed) ----
__device__ float g_scores[NTOK];
__device__ float g_probs[NTOK];
__device__ __nv_bfloat16 g_xh[(size_t)NTOK * HSZ];
__device__ __nv_bfloat16 g_xl[(size_t)NTOK * HSZ];
__device__ __nv_bfloat16 g_wh[(size_t)HSZ * HSZ];
__device__ __nv_bfloat16 g_wl[(size_t)HSZ * HSZ];

// ---------------------------------------------------------------------------
__device__ __forceinline__ uint32_t s2u(const void* p) {
    return (uint32_t)__cvta_generic_to_shared(p);
}

__device__ __forceinline__ void cp16(uint32_t saddr, const void* gptr) {
    asm volatile("cp.async.cg.shared.global [%0], [%1], 16;"
                 :: "r"(saddr), "l"(gptr) : "memory");
}

#define LDMX4(r0, r1, r2, r3, addr) \
    asm volatile("ldmatrix.sync.aligned.m8n8.x4.shared.b16 {%0,%1,%2,%3}, [%4];" \
                 : "=r"(r0), "=r"(r1), "=r"(r2), "=r"(r3) : "r"(addr))

#define MMA16816(d, a, b) \
    asm volatile("mma.sync.aligned.m16n8k16.row.col.f32.bf16.bf16.f32 " \
                 "{%0,%1,%2,%3}, {%4,%5,%6,%7}, {%8,%9}, {%0,%1,%2,%3};" \
                 : "+f"((d)[0]), "+f"((d)[1]), "+f"((d)[2]), "+f"((d)[3]) \
                 : "r"((a)[0]), "r"((a)[1]), "r"((a)[2]), "r"((a)[3]), \
                   "r"((b)[0]), "r"((b)[1]))

__device__ __forceinline__ float ftanh(float v) {
    float e = __expf(2.0f * v);
    return 1.0f - 2.0f / (e + 1.0f);
}

// ---------------------------------------------------------------------------
// Kernel 0: fp32 -> bf16 hi/lo split
// ---------------------------------------------------------------------------
__global__ __launch_bounds__(256) void convert_kernel(
    const float* __restrict__ src, __nv_bfloat16* __restrict__ hi,
    __nv_bfloat16* __restrict__ lo, size_t n)
{
    size_t i = ((size_t)blockIdx.x * blockDim.x + threadIdx.x) * 4;
    if (i >= n) return;
    float4 v = *(const float4*)(src + i);
    float a[4] = {v.x, v.y, v.z, v.w};
    __nv_bfloat16 h[4], l[4];
    #pragma unroll
    for (int j = 0; j < 4; j++) {
        h[j] = __float2bfloat16(a[j]);
        l[j] = __float2bfloat16(a[j] - __bfloat162float(h[j]));
    }
    ((__nv_bfloat162*)(hi + i))[0] = __halves2bfloat162(h[0], h[1]);
    ((__nv_bfloat162*)(hi + i))[1] = __halves2bfloat162(h[2], h[3]);
    ((__nv_bfloat162*)(lo + i))[0] = __halves2bfloat162(l[0], l[1]);
    ((__nv_bfloat162*)(lo + i))[1] = __halves2bfloat162(l[2], l[3]);
}

// ---------------------------------------------------------------------------
// Stage loader: A (128 x 32 bf16, hi+lo) + B (256 x 32 bf16, hi+lo).
// Row pitch 80B: chunk c of row r at 80r+16c -> bank group (5r+c)&7,
// distinct for any 8 consecutive rows at fixed c (conflict-free ldmatrix).
// ---------------------------------------------------------------------------
__device__ __forceinline__ void load_stage(uint32_t sb, int t0, int n0, int k0, int tid)
{
    {   // A: 128 rows x 4 chunks = 512 slots, one per thread
        int r = tid >> 2, c = tid & 3;
        uint32_t so = (uint32_t)(r * PITCH + c * 16);
        size_t gi = (size_t)(t0 + r) * HSZ + k0 + c * 8;
        cp16(sb + AHI + so, g_xh + gi);
        cp16(sb + ALO + so, g_xl + gi);
    }
    #pragma unroll
    for (int it = 0; it < 2; it++) {   // B: 256 rows x 4 chunks = 1024 slots
        int idx = tid + it * 512;
        int r = idx >> 2, c = idx & 3;
        uint32_t so = (uint32_t)(r * PITCH + c * 16);
        size_t gi = (size_t)(n0 + r) * HSZ + k0 + c * 8;
        cp16(sb + BHI + so, g_wh + gi);
        cp16(sb + BLO + so, g_wl + gi);
    }
    asm volatile("cp.async.commit_group;" ::: "memory");
}

// ---------------------------------------------------------------------------
// Kernel A: fused scores GEMM, bf16x3 split precision on mma.sync HMMA.
// 3-stage cp.async pipeline, ONE barrier per K-stage:
//   wait_group(1) -> barrier -> issue load(ks+2) -> compute(ks)
// Barrier proves all warps finished compute(ks-1), so writing buffer
// (ks+2)%3 == (ks-1)%3 is safe while everyone reads buffer ks%3.
// ---------------------------------------------------------------------------
__global__ void __launch_bounds__(512, 1) gemm_scores_kernel(
    const float* __restrict__ bias, const float* __restrict__ key)
{
    extern __shared__ char smem[];
    const uint32_t sbase = s2u(smem);
    const int tid = threadIdx.x;
    const int wid = tid >> 5;
    const int lid = tid & 31;
    const int wm  = wid & 3;          // warp m index (4)
    const int wn  = wid >> 2;         // warp n index (4)
    const int t0  = blockIdx.x * M_CTA;

    float* s_score = (float*)(smem + SOFF_SCORE);
    float* s_key   = (float*)(smem + SOFF_KEY);
    float* s_bias  = (float*)(smem + SOFF_BIAS);
    for (int i = tid; i < HSZ; i += 512) {
        s_key[i]  = key[i];
        s_bias[i] = bias[i];
    }
    if (tid < M_CTA) s_score[tid] = 0.0f;

    // ldmatrix lane geometry
    const int g  = lid >> 3;          // quad-group 0..3
    const int r8 = lid & 7;
    const int a_row  = wm * 32 + (g & 1) * 8 + r8;   // + i*16
    const int a_kh   = g >> 1;                       // k8-half
    const int b_rowb = wn * 64 + (g >> 1) * 8 + r8;  // + nh*32 + p*16
    const int b_kh   = g & 1;

    float score_p[2][2];              // per-thread row partials [i][mhalf]

    for (int nc = 0; nc < NCHUNK; nc++) {
        const int n0 = nc * N_CHUNK;
        float acc[2][8][4];
        #pragma unroll
        for (int i = 0; i < 2; i++)
            #pragma unroll
            for (int j = 0; j < 8; j++)
                #pragma unroll
                for (int c = 0; c < 4; c++) acc[i][j][c] = 0.0f;

        __syncthreads();              // prior chunk fully consumed buffers
        load_stage(sbase + SOFF_STAGE,                  t0, n0, 0,      tid);
        load_stage(sbase + SOFF_STAGE + STAGE_BYTES,    t0, n0, BK,     tid);

        for (int ks = 0; ks < NKSTAGE; ks++) {
            const uint32_t stg = sbase + SOFF_STAGE
                               + (uint32_t)(ks % NSTAGE) * STAGE_BYTES;

            if (ks + 1 < NKSTAGE)
                asm volatile("cp.async.wait_group 1;" ::: "memory");
            else
                asm volatile("cp.async.wait_group 0;" ::: "memory");
            __syncthreads();

            if (ks + 2 < NKSTAGE)
                load_stage(sbase + SOFF_STAGE
                           + (uint32_t)((ks + 2) % NSTAGE) * STAGE_BYTES,
                           t0, n0, (ks + 2) * BK, tid);

            #pragma unroll
            for (int k16 = 0; k16 < 2; k16++) {
                uint32_t ah[2][4], al[2][4];
                #pragma unroll
                for (int i = 0; i < 2; i++) {
                    uint32_t off = (uint32_t)((a_row + i * 16) * PITCH
                                            + 16 * (k16 * 2 + a_kh));
                    LDMX4(ah[i][0], ah[i][1], ah[i][2], ah[i][3], stg + AHI + off);
                    LDMX4(al[i][0], al[i][1], al[i][2], al[i][3], stg + ALO + off);
                }
                #pragma unroll
                for (int nh = 0; nh < 2; nh++) {
                    uint32_t bh[4][2], bl[4][2];
                    #pragma unroll
                    for (int p = 0; p < 2; p++) {
                        uint32_t off = (uint32_t)((b_rowb + nh * 32 + p * 16) * PITCH
                                                + 16 * (k16 * 2 + b_kh));
                        LDMX4(bh[2*p][0], bh[2*p][1], bh[2*p+1][0], bh[2*p+1][1],
                              stg + BHI + off);
                        LDMX4(bl[2*p][0], bl[2*p][1], bl[2*p+1][0], bl[2*p+1][1],
                              stg + BLO + off);
                    }
                    #pragma unroll
                    for (int i = 0; i < 2; i++)
                        #pragma unroll
                        for (int j = 0; j < 4; j++) {
                            MMA16816(acc[i][nh * 4 + j], ah[i], bh[j]);  // hi*hi
                            MMA16816(acc[i][nh * 4 + j], ah[i], bl[j]);  // hi*lo
                            MMA16816(acc[i][nh * 4 + j], al[i], bh[j]);  // lo*hi
                        }
                }
            }
        }

        // epilogue: tanh(acc + bias) * key, reduce over n into s_score
        #pragma unroll
        for (int i = 0; i < 2; i++)
            #pragma unroll
            for (int mh = 0; mh < 2; mh++) score_p[i][mh] = 0.0f;

        #pragma unroll
        for (int i = 0; i < 2; i++)
            #pragma unroll
            for (int j = 0; j < 8; j++)
                #pragma unroll
                for (int c = 0; c < 4; c++) {
                    int n = n0 + wn * 64 + j * 8 + (lid & 3) * 2 + (c & 1);
                    float v = ftanh(acc[i][j][c] + s_bias[n]) * s_key[n];
                    score_p[i][c >> 1] += v;
                }

        #pragma unroll
        for (int i = 0; i < 2; i++)
            #pragma unroll
            for (int mh = 0; mh < 2; mh++) {
                float v = score_p[i][mh];
                v += __shfl_xor_sync(0xffffffffu, v, 1);
                v += __shfl_xor_sync(0xffffffffu, v, 2);
                if ((lid & 3) == 0) {
                    int m = wm * 32 + i * 16 + mh * 8 + (lid >> 2);
                    atomicAdd(&s_score[m], v);
                }
            }
    }

    __syncthreads();
    if (tid < M_CTA) g_scores[t0 + tid] = s_score[tid];
}

// ---------------------------------------------------------------------------
// Kernel B1: per-batch masked softmax over scores -> probs (0 beyond length).
// ---------------------------------------------------------------------------
__global__ __launch_bounds__(256) void softmax_kernel(const int* __restrict__ lengths)
{
    __shared__ float red[256];
    const int b = blockIdx.x;
    const int len = lengths[b];
    const float* sc = g_scores + b * SSZ;
    const int tid = threadIdx.x;

    float m = -1e30f;
    for (int s = tid; s < len; s += 256) m = fmaxf(m, sc[s]);
    red[tid] = m;
    __syncthreads();
    for (int o = 128; o > 0; o >>= 1) {
        if (tid < o) red[tid] = fmaxf(red[tid], red[tid + o]);
        __syncthreads();
    }
    m = red[0];
    __syncthreads();

    float sum = 0.f;
    for (int s = tid; s < len; s += 256) sum += expf(sc[s] - m);
    red[tid] = sum;
    __syncthreads();
    for (int o = 128; o > 0; o >>= 1) {
        if (tid < o) red[tid] += red[tid + o];
        __syncthreads();
    }
    const float inv = 1.0f / red[0];

    for (int s = tid; s < SSZ; s += 256)
        g_probs[b * SSZ + s] = (s < len) ? expf(sc[s] - m) * inv : 0.f;
}

// ---------------------------------------------------------------------------
// Kernel B2: out[b,h] = sum_{s<len} probs[b,s] * x[b,s,h]
// ---------------------------------------------------------------------------
__global__ __launch_bounds__(128) void output_kernel(
    const float* __restrict__ x, const int* __restrict__ lengths,
    float* __restrict__ out)
{
    const int b = blockIdx.y;
    const int h = blockIdx.x * 128 + threadIdx.x;
    const int len = lengths[b];
    const float* xb = x + (size_t)b * SSZ * HSZ + h;
    const float* pb = g_probs + b * SSZ;

    float a0 = 0.f, a1 = 0.f, a2 = 0.f, a3 = 0.f;
    int s = 0;
    for (; s + 4 <= len; s += 4) {
        a0 += pb[s + 0] * xb[(size_t)(s + 0) * HSZ];
        a1 += pb[s + 1] * xb[(size_t)(s + 1) * HSZ];
        a2 += pb[s + 2] * xb[(size_t)(s + 2) * HSZ];
        a3 += pb[s + 3] * xb[(size_t)(s + 3) * HSZ];
    }
    for (; s < len; s++) a0 += pb[s] * xb[(size_t)s * HSZ];

    out[b * HSZ + h] = (a0 + a1) + (a2 + a3);
}

// ---------------------------------------------------------------------------
extern "C" void kernel_launch(void* const* d_in, const int* in_sizes, int n_in,
                              void* d_out, int out_size)
{
    const float* x       = (const float*)d_in[0];
    const int*   lengths = (const int*)  d_in[1];
    const float* W       = (const float*)d_in[2];
    const float* bias    = (const float*)d_in[3];
    const float* key     = (const float*)d_in[4];
    float* out = (float*)d_out;

    cudaFuncSetAttribute(gemm_scores_kernel,
                         cudaFuncAttributeMaxDynamicSharedMemorySize, SMEM_TOTAL);

    __nv_bfloat16 *xh, *xl, *wh, *wl;
    cudaGetSymbolAddress((void**)&xh, g_xh);
    cudaGetSymbolAddress((void**)&xl, g_xl);
    cudaGetSymbolAddress((void**)&wh, g_wh);
    cudaGetSymbolAddress((void**)&wl, g_wl);

    size_t nx = (size_t)NTOK * HSZ;
    size_t nw = (size_t)HSZ * HSZ;
    convert_kernel<<<(unsigned)(nx / (256 * 4)), 256>>>(x, xh, xl, nx);
    convert_kernel<<<(unsigned)(nw / (256 * 4)), 256>>>(W, wh, wl, nw);

    gemm_scores_kernel<<<NTOK / M_CTA, 512, SMEM_TOTAL>>>(bias, key);
    softmax_kernel<<<BSZ, 256>>>(lengths);
    output_kernel<<<dim3(HSZ / 128, BSZ), 128>>>(x, lengths, out);
}

// round 7
// speedup vs baseline: 1.6259x; 1.6259x over previous
#include <cuda_runtime.h>
#include <cuda_bf16.h>
#include <cstdint>

#define BSZ 16
#define SSZ 4096
#define HSZ 1024
#define NTOK (BSZ * SSZ)

#define M_CTA 128
#define N_CHUNK 256
#define NCHUNK (HSZ / N_CHUNK)     // 4
#define BK 32
#define NKSTAGE (HSZ / BK)         // 32 K-stages per chunk
#define NSTAGES_TOT (NCHUNK * NKSTAGE)  // 128 global stages
#define NBUF 4                     // smem buffer ring depth

// gmem tiled blocks (contiguous, pre-swizzled smem images)
#define A_BLK 16384                // 128 rows x 64B  (hi 8K | lo 8K)
#define B_BLK 32768                // 256 rows x 64B  (hi 16K | lo 16K)

// smem layout (bytes)
#define SOFF_SCORE 0               // float[128]
#define SOFF_KEY   512             // float[1024]
#define SOFF_BIAS  4608            // float[1024]
#define SOFF_MBAR  8640            // 4 x 8B mbarriers
#define SOFF_STAGE 9216
#define STG_AHI 0
#define STG_ALO 8192
#define STG_B   16384              // B hi 16K then lo 16K (one gmem block)
#define STAGE_BYTES 49152
#define SMEM_TOTAL (SOFF_STAGE + NBUF * STAGE_BYTES)   // 205824

// ---- scratch (no allocations allowed) ----
__device__ float g_scores[NTOK];
__device__ float g_probs[NTOK];
// A: [tile 512][kstage 32][16KB image]   B: [chunk 4][kstage 32][32KB image]
__device__ __align__(1024) unsigned char g_a[(size_t)512 * 32 * A_BLK]; // 268 MB
__device__ __align__(1024) unsigned char g_b[(size_t)4 * 32 * B_BLK];   // 4 MB

// ---------------------------------------------------------------------------
__device__ __forceinline__ uint32_t s2u(const void* p) {
    return (uint32_t)__cvta_generic_to_shared(p);
}

#define LDMX4(r0, r1, r2, r3, addr) \
    asm volatile("ldmatrix.sync.aligned.m8n8.x4.shared.b16 {%0,%1,%2,%3}, [%4];" \
                 : "=r"(r0), "=r"(r1), "=r"(r2), "=r"(r3) : "r"(addr))

#define MMA16816(d, a, b) \
    asm volatile("mma.sync.aligned.m16n8k16.row.col.f32.bf16.bf16.f32 " \
                 "{%0,%1,%2,%3}, {%4,%5,%6,%7}, {%8,%9}, {%0,%1,%2,%3};" \
                 : "+f"((d)[0]), "+f"((d)[1]), "+f"((d)[2]), "+f"((d)[3]) \
                 : "r"((a)[0]), "r"((a)[1]), "r"((a)[2]), "r"((a)[3]), \
                   "r"((b)[0]), "r"((b)[1]))

__device__ __forceinline__ void mbar_init(uint32_t mbar, uint32_t cnt) {
    asm volatile("mbarrier.init.shared.b64 [%0], %1;" :: "r"(mbar), "r"(cnt) : "memory");
}

__device__ __forceinline__ void mbar_expect_tx(uint32_t mbar, uint32_t bytes) {
    asm volatile("mbarrier.arrive.expect_tx.shared.b64 _, [%0], %1;"
                 :: "r"(mbar), "r"(bytes) : "memory");
}

__device__ __forceinline__ void bulk_g2s(uint32_t sdst, const void* gsrc,
                                         uint32_t bytes, uint32_t mbar) {
    asm volatile("cp.async.bulk.shared::cluster.global.mbarrier::complete_tx::bytes "
                 "[%0], [%1], %2, [%3];"
                 :: "r"(sdst), "l"(gsrc), "r"(bytes), "r"(mbar) : "memory");
}

__device__ __forceinline__ void mbar_wait(uint32_t mbar, uint32_t phase) {
    uint32_t done;
    asm volatile(
        "{\n\t.reg .pred p;\n\t"
        "mbarrier.try_wait.parity.acquire.cta.shared::cta.b64 p, [%1], %2;\n\t"
        "selp.b32 %0, 1, 0, p;\n\t}"
        : "=r"(done) : "r"(mbar), "r"(phase) : "memory");
    if (!done) {
        asm volatile(
            "{\n\t.reg .pred P1;\n\t"
            "WAIT_LOOP_%=:\n\t"
            "mbarrier.try_wait.parity.acquire.cta.shared::cta.b64 P1, [%0], %1, 0x989680;\n\t"
            "@P1 bra.uni WAIT_DONE_%=;\n\t"
            "bra.uni WAIT_LOOP_%=;\n\t"
            "WAIT_DONE_%=:\n\t}"
            :: "r"(mbar), "r"(phase) : "memory");
    }
}

__device__ __forceinline__ float ftanh(float v) {
    float e = __expf(2.0f * v);
    return 1.0f - 2.0f / (e + 1.0f);
}

// ---------------------------------------------------------------------------
// Convert kernels: fp32 -> bf16 hi/lo, written as pre-tiled pre-swizzled
// smem images so the GEMM can fetch one contiguous block per stage.
// Swizzle: 64B rows, 16B chunk c stored at c ^ ((r>>1)&3)  (ldmatrix
// conflict-free: banks (4r + c')&7 distinct over any aligned 8 rows).
// ---------------------------------------------------------------------------
__global__ __launch_bounds__(256) void convert_a_kernel(const float* __restrict__ x)
{
    int id = blockIdx.x * 256 + threadIdx.x;      // (t, ks, c)
    int c  = id & 3;
    int ks = (id >> 2) & 31;
    int t  = id >> 7;
    const float* src = x + (size_t)t * HSZ + ks * 32 + c * 8;
    float4 v0 = *(const float4*)src;
    float4 v1 = *(const float4*)(src + 4);
    float a[8] = {v0.x, v0.y, v0.z, v0.w, v1.x, v1.y, v1.z, v1.w};

    uint4 hv, lv;
    __nv_bfloat16* hp = (__nv_bfloat16*)&hv;
    __nv_bfloat16* lp = (__nv_bfloat16*)&lv;
    #pragma unroll
    for (int j = 0; j < 8; j++) {
        hp[j] = __float2bfloat16(a[j]);
        lp[j] = __float2bfloat16(a[j] - __bfloat162float(hp[j]));
    }
    int r = t & 127;
    size_t off = ((size_t)(t >> 7) * 32 + ks) * A_BLK
               + (size_t)r * 64 + ((c ^ ((r >> 1) & 3)) << 4);
    *(uint4*)(g_a + off)        = hv;
    *(uint4*)(g_a + off + 8192) = lv;
}

__global__ __launch_bounds__(256) void convert_b_kernel(const float* __restrict__ W)
{
    int id = blockIdx.x * 256 + threadIdx.x;      // (n, ks, c)
    int c  = id & 3;
    int ks = (id >> 2) & 31;
    int n  = id >> 7;
    const float* src = W + (size_t)n * HSZ + ks * 32 + c * 8;
    float4 v0 = *(const float4*)src;
    float4 v1 = *(const float4*)(src + 4);
    float a[8] = {v0.x, v0.y, v0.z, v0.w, v1.x, v1.y, v1.z, v1.w};

    uint4 hv, lv;
    __nv_bfloat16* hp = (__nv_bfloat16*)&hv;
    __nv_bfloat16* lp = (__nv_bfloat16*)&lv;
    #pragma unroll
    for (int j = 0; j < 8; j++) {
        hp[j] = __float2bfloat16(a[j]);
        lp[j] = __float2bfloat16(a[j] - __bfloat162float(hp[j]));
    }
    int r = n & 255;
    size_t off = ((size_t)(n >> 8) * 32 + ks) * B_BLK
               + (size_t)r * 64 + ((c ^ ((r >> 1) & 3)) << 4);
    *(uint4*)(g_b + off)         = hv;
    *(uint4*)(g_b + off + 16384) = lv;
}

// ---------------------------------------------------------------------------
// Kernel A: fused scores GEMM, bf16x3 split precision on mma.sync HMMA.
// Feeds via cp.async.bulk (2 bulk ops/stage, issued by tid 0) into a 4-deep
// smem ring; mbarrier complete_tx signals stage readiness. One barrier/stage.
// ---------------------------------------------------------------------------
__global__ void __launch_bounds__(512, 1) gemm_scores_kernel(
    const float* __restrict__ bias, const float* __restrict__ key)
{
    extern __shared__ char smem[];
    const uint32_t sbase = s2u(smem);
    const int tid = threadIdx.x;
    const int wid = tid >> 5;
    const int lid = tid & 31;
    const int wm  = wid & 3;          // warp m index (4)
    const int wn  = wid >> 2;         // warp n index (4)
    const int t0  = blockIdx.x * M_CTA;

    float* s_score = (float*)(smem + SOFF_SCORE);
    float* s_key   = (float*)(smem + SOFF_KEY);
    float* s_bias  = (float*)(smem + SOFF_BIAS);
    for (int i = tid; i < HSZ; i += 512) {
        s_key[i]  = key[i];
        s_bias[i] = bias[i];
    }
    if (tid < M_CTA) s_score[tid] = 0.0f;
    if (tid == 0) {
        #pragma unroll
        for (int i = 0; i < NBUF; i++) mbar_init(sbase + SOFF_MBAR + i * 8, 1);
    }
    __syncthreads();

    // prologue: stages 0..2
    if (tid == 0) {
        #pragma unroll
        for (int s = 0; s < NBUF - 1; s++) {
            uint32_t mb = sbase + SOFF_MBAR + s * 8;
            mbar_expect_tx(mb, STAGE_BYTES);
            bulk_g2s(sbase + SOFF_STAGE + s * STAGE_BYTES,
                     g_a + ((size_t)blockIdx.x * 32 + (s & 31)) * A_BLK, A_BLK, mb);
            bulk_g2s(sbase + SOFF_STAGE + s * STAGE_BYTES + STG_B,
                     g_b + ((size_t)(s >> 5) * 32 + (s & 31)) * B_BLK, B_BLK, mb);
        }
    }

    // ldmatrix lane geometry
    const int g  = lid >> 3;          // quad-group 0..3
    const int r8 = lid & 7;
    const int a_row  = wm * 32 + (g & 1) * 8 + r8;   // + i*16
    const int a_kh   = g >> 1;                       // k8-half
    const int b_rowb = wn * 64 + (g >> 1) * 8 + r8;  // + nh*32 + p*16
    const int b_kh   = g & 1;
    const int a_xm   = (a_row  >> 1) & 3;            // xor mask (invariant to +16/+32)
    const int b_xm   = (b_rowb >> 1) & 3;

    float acc[2][8][4];
    float score_p[2][2];

    for (int gs = 0; gs < NSTAGES_TOT; gs++) {
        const int ks = gs & 31;
        const uint32_t stg = sbase + SOFF_STAGE + (uint32_t)(gs & 3) * STAGE_BYTES;

        if (ks == 0) {
            #pragma unroll
            for (int i = 0; i < 2; i++)
                #pragma unroll
                for (int j = 0; j < 8; j++)
                    #pragma unroll
                    for (int c = 0; c < 4; c++) acc[i][j][c] = 0.0f;
        }

        mbar_wait(sbase + SOFF_MBAR + (gs & 3) * 8, (gs >> 2) & 1);

        // issue stage gs+3 into the buffer freed at stage gs-1
        if (tid == 0 && gs + 3 < NSTAGES_TOT) {
            const int s = gs + 3;
            uint32_t mb = sbase + SOFF_MBAR + (s & 3) * 8;
            mbar_expect_tx(mb, STAGE_BYTES);
            bulk_g2s(sbase + SOFF_STAGE + (uint32_t)(s & 3) * STAGE_BYTES,
                     g_a + ((size_t)blockIdx.x * 32 + (s & 31)) * A_BLK, A_BLK, mb);
            bulk_g2s(sbase + SOFF_STAGE + (uint32_t)(s & 3) * STAGE_BYTES + STG_B,
                     g_b + ((size_t)(s >> 5) * 32 + (s & 31)) * B_BLK, B_BLK, mb);
        }

        #pragma unroll
        for (int k16 = 0; k16 < 2; k16++) {
            uint32_t ah[2][4], al[2][4];
            const uint32_t a_csw = (uint32_t)(((k16 * 2 + a_kh) ^ a_xm) << 4);
            #pragma unroll
            for (int i = 0; i < 2; i++) {
                uint32_t off = (uint32_t)((a_row + i * 16) << 6) + a_csw;
                LDMX4(ah[i][0], ah[i][1], ah[i][2], ah[i][3], stg + STG_AHI + off);
                LDMX4(al[i][0], al[i][1], al[i][2], al[i][3], stg + STG_ALO + off);
            }
            const uint32_t b_csw = (uint32_t)(((k16 * 2 + b_kh) ^ b_xm) << 4);
            #pragma unroll
            for (int nh = 0; nh < 2; nh++) {
                uint32_t bh[4][2], bl[4][2];
                #pragma unroll
                for (int p = 0; p < 2; p++) {
                    uint32_t off = (uint32_t)((b_rowb + nh * 32 + p * 16) << 6) + b_csw;
                    LDMX4(bh[2*p][0], bh[2*p][1], bh[2*p+1][0], bh[2*p+1][1],
                          stg + STG_B + off);
                    LDMX4(bl[2*p][0], bl[2*p][1], bl[2*p+1][0], bl[2*p+1][1],
                          stg + STG_B + 16384 + off);
                }
                #pragma unroll
                for (int i = 0; i < 2; i++)
                    #pragma unroll
                    for (int j = 0; j < 4; j++) {
                        MMA16816(acc[i][nh * 4 + j], ah[i], bh[j]);  // hi*hi
                        MMA16816(acc[i][nh * 4 + j], ah[i], bl[j]);  // hi*lo
                        MMA16816(acc[i][nh * 4 + j], al[i], bh[j]);  // lo*hi
                    }
            }
        }

        if (ks == 31) {
            // epilogue for this n-chunk: tanh(acc+bias)*key -> score partials
            const int n0 = (gs >> 5) * N_CHUNK;
            #pragma unroll
            for (int i = 0; i < 2; i++)
                #pragma unroll
                for (int mh = 0; mh < 2; mh++) score_p[i][mh] = 0.0f;

            #pragma unroll
            for (int i = 0; i < 2; i++)
                #pragma unroll
                for (int j = 0; j < 8; j++)
                    #pragma unroll
                    for (int c = 0; c < 4; c++) {
                        int n = n0 + wn * 64 + j * 8 + (lid & 3) * 2 + (c & 1);
                        float v = ftanh(acc[i][j][c] + s_bias[n]) * s_key[n];
                        score_p[i][c >> 1] += v;
                    }

            #pragma unroll
            for (int i = 0; i < 2; i++)
                #pragma unroll
                for (int mh = 0; mh < 2; mh++) {
                    float v = score_p[i][mh];
                    v += __shfl_xor_sync(0xffffffffu, v, 1);
                    v += __shfl_xor_sync(0xffffffffu, v, 2);
                    if ((lid & 3) == 0) {
                        int m = wm * 32 + i * 16 + mh * 8 + (lid >> 2);
                        atomicAdd(&s_score[m], v);
                    }
                }
        }

        __syncthreads();   // all warps done with this buffer -> reusable
    }

    if (tid < M_CTA) g_scores[t0 + tid] = s_score[tid];
}

// ---------------------------------------------------------------------------
// Kernel B1: per-batch masked softmax over scores -> probs (0 beyond length).
// ---------------------------------------------------------------------------
__global__ __launch_bounds__(256) void softmax_kernel(const int* __restrict__ lengths)
{
    __shared__ float red[256];
    const int b = blockIdx.x;
    const int len = lengths[b];
    const float* sc = g_scores + b * SSZ;
    const int tid = threadIdx.x;

    float m = -1e30f;
    for (int s = tid; s < len; s += 256) m = fmaxf(m, sc[s]);
    red[tid] = m;
    __syncthreads();
    for (int o = 128; o > 0; o >>= 1) {
        if (tid < o) red[tid] = fmaxf(red[tid], red[tid + o]);
        __syncthreads();
    }
    m = red[0];
    __syncthreads();

    float sum = 0.f;
    for (int s = tid; s < len; s += 256) sum += expf(sc[s] - m);
    red[tid] = sum;
    __syncthreads();
    for (int o = 128; o > 0; o >>= 1) {
        if (tid < o) red[tid] += red[tid + o];
        __syncthreads();
    }
    const float inv = 1.0f / red[0];

    for (int s = tid; s < SSZ; s += 256)
        g_probs[b * SSZ + s] = (s < len) ? expf(sc[s] - m) * inv : 0.f;
}

// ---------------------------------------------------------------------------
// Kernel B2: out[b,h] = sum_{s<len} probs[b,s] * x[b,s,h]
// ---------------------------------------------------------------------------
__global__ __launch_bounds__(128) void output_kernel(
    const float* __restrict__ x, const int* __restrict__ lengths,
    float* __restrict__ out)
{
    const int b = blockIdx.y;
    const int h = blockIdx.x * 128 + threadIdx.x;
    const int len = lengths[b];
    const float* xb = x + (size_t)b * SSZ * HSZ + h;
    const float* pb = g_probs + b * SSZ;

    float a0 = 0.f, a1 = 0.f, a2 = 0.f, a3 = 0.f;
    int s = 0;
    for (; s + 4 <= len; s += 4) {
        a0 += pb[s + 0] * xb[(size_t)(s + 0) * HSZ];
        a1 += pb[s + 1] * xb[(size_t)(s + 1) * HSZ];
        a2 += pb[s + 2] * xb[(size_t)(s + 2) * HSZ];
        a3 += pb[s + 3] * xb[(size_t)(s + 3) * HSZ];
    }
    for (; s < len; s++) a0 += pb[s] * xb[(size_t)s * HSZ];

    out[b * HSZ + h] = (a0 + a1) + (a2 + a3);
}

// ---------------------------------------------------------------------------
extern "C" void kernel_launch(void* const* d_in, const int* in_sizes, int n_in,
                              void* d_out, int out_size)
{
    const float* x       = (const float*)d_in[0];
    const int*   lengths = (const int*)  d_in[1];
    const float* W       = (const float*)d_in[2];
    const float* bias    = (const float*)d_in[3];
    const float* key     = (const float*)d_in[4];
    float* out = (float*)d_out;

    cudaFuncSetAttribute(gemm_scores_kernel,
                         cudaFuncAttributeMaxDynamicSharedMemorySize, SMEM_TOTAL);

    // x: 64K tokens x 32 ks x 4 chunks = 8.4M threads; W: 1024 x 32 x 4
    convert_a_kernel<<<(NTOK * 32 * 4) / 256, 256>>>(x);
    convert_b_kernel<<<(HSZ * 32 * 4) / 256, 256>>>(W);

    gemm_scores_kernel<<<NTOK / M_CTA, 512, SMEM_TOTAL>>>(bias, key);
    softmax_kernel<<<BSZ, 256>>>(lengths);
    output_kernel<<<dim3(HSZ / 128, BSZ), 128>>>(x, lengths, out);
}

// round 9
// speedup vs baseline: 1.7341x; 1.0665x over previous
#include <cuda_runtime.h>
#include <cuda_bf16.h>
#include <cstdint>

#define BSZ 16
#define SSZ 4096
#define HSZ 1024
#define NTOK (BSZ * SSZ)

#define M_CTA 128
#define N_CHUNK 256
#define NCHUNK (HSZ / N_CHUNK)     // 4
#define NSPLIT 2                   // n-chunks split across 2 CTAs per tile
#define BK 32
#define NKSTAGE (HSZ / BK)         // 32 K-stages per chunk
#define NSTAGES_CTA ((NCHUNK / NSPLIT) * NKSTAGE)  // 64 stages per CTA
#define NBUF 4                     // smem buffer ring depth

// gmem tiled blocks (contiguous, pre-swizzled smem images)
#define A_BLK 16384                // 128 rows x 64B  (hi 8K | lo 8K)
#define B_BLK 32768                // 256 rows x 64B  (hi 16K | lo 16K)

// smem layout (bytes)
#define SOFF_SCORE 0               // float[128]
#define SOFF_KEY   512             // float[1024]
#define SOFF_BIAS  4608            // float[1024]
#define SOFF_MBAR  8640            // 4 x 8B mbarriers
#define SOFF_STAGE 9216
#define STG_AHI 0
#define STG_ALO 8192
#define STG_B   16384              // B hi 16K then lo 16K (one gmem block)
#define STAGE_BYTES 49152
#define SMEM_TOTAL (SOFF_STAGE + NBUF * STAGE_BYTES)   // 205824

// ---- scratch (no allocations allowed) ----
__device__ float g_scores_part[NSPLIT * NTOK];
__device__ float g_probs[NTOK];
// A: [tile 512][kstage 32][16KB image]   B: [chunk 4][kstage 32][32KB image]
__device__ __align__(1024) unsigned char g_a[(size_t)512 * 32 * A_BLK]; // 268 MB
__device__ __align__(1024) unsigned char g_b[(size_t)4 * 32 * B_BLK];   // 4 MB

// ---------------------------------------------------------------------------
__device__ __forceinline__ uint32_t s2u(const void* p) {
    return (uint32_t)__cvta_generic_to_shared(p);
}

#define LDMX4(r0, r1, r2, r3, addr) \
    asm volatile("ldmatrix.sync.aligned.m8n8.x4.shared.b16 {%0,%1,%2,%3}, [%4];" \
                 : "=r"(r0), "=r"(r1), "=r"(r2), "=r"(r3) : "r"(addr))

#define MMA16816(d, a, b) \
    asm volatile("mma.sync.aligned.m16n8k16.row.col.f32.bf16.bf16.f32 " \
                 "{%0,%1,%2,%3}, {%4,%5,%6,%7}, {%8,%9}, {%0,%1,%2,%3};" \
                 : "+f"((d)[0]), "+f"((d)[1]), "+f"((d)[2]), "+f"((d)[3]) \
                 : "r"((a)[0]), "r"((a)[1]), "r"((a)[2]), "r"((a)[3]), \
                   "r"((b)[0]), "r"((b)[1]))

__device__ __forceinline__ void mbar_init(uint32_t mbar, uint32_t cnt) {
    asm volatile("mbarrier.init.shared.b64 [%0], %1;" :: "r"(mbar), "r"(cnt) : "memory");
}

__device__ __forceinline__ void mbar_expect_tx(uint32_t mbar, uint32_t bytes) {
    asm volatile("mbarrier.arrive.expect_tx.shared.b64 _, [%0], %1;"
                 :: "r"(mbar), "r"(bytes) : "memory");
}

__device__ __forceinline__ void bulk_g2s(uint32_t sdst, const void* gsrc,
                                         uint32_t bytes, uint32_t mbar) {
    asm volatile("cp.async.bulk.shared::cluster.global.mbarrier::complete_tx::bytes "
                 "[%0], [%1], %2, [%3];"
                 :: "r"(sdst), "l"(gsrc), "r"(bytes), "r"(mbar) : "memory");
}

__device__ __forceinline__ void mbar_wait(uint32_t mbar, uint32_t phase) {
    uint32_t done;
    asm volatile(
        "{\n\t.reg .pred p;\n\t"
        "mbarrier.try_wait.parity.acquire.cta.shared::cta.b64 p, [%1], %2;\n\t"
        "selp.b32 %0, 1, 0, p;\n\t}"
        : "=r"(done) : "r"(mbar), "r"(phase) : "memory");
    if (!done) {
        asm volatile(
            "{\n\t.reg .pred P1;\n\t"
            "WAIT_LOOP_%=:\n\t"
            "mbarrier.try_wait.parity.acquire.cta.shared::cta.b64 P1, [%0], %1, 0x989680;\n\t"
            "@P1 bra.uni WAIT_DONE_%=;\n\t"
            "bra.uni WAIT_LOOP_%=;\n\t"
            "WAIT_DONE_%=:\n\t}"
            :: "r"(mbar), "r"(phase) : "memory");
    }
}

__device__ __forceinline__ float ftanh(float v) {
    float e = __expf(2.0f * v);
    return 1.0f - 2.0f / (e + 1.0f);
}

// ---------------------------------------------------------------------------
// Convert kernels: fp32 -> bf16 hi/lo, written as pre-tiled pre-swizzled
// smem images so the GEMM can fetch one contiguous block per stage.
// Swizzle: 64B rows, 16B chunk c stored at c ^ ((r>>1)&3)  (ldmatrix
// conflict-free: banks (4r + c')&7 distinct over any aligned 8 rows).
// ---------------------------------------------------------------------------
__global__ __launch_bounds__(256) void convert_a_kernel(const float* __restrict__ x)
{
    int id = blockIdx.x * 256 + threadIdx.x;      // (t, ks, c)
    int c  = id & 3;
    int ks = (id >> 2) & 31;
    int t  = id >> 7;
    const float* src = x + (size_t)t * HSZ + ks * 32 + c * 8;
    float4 v0 = *(const float4*)src;
    float4 v1 = *(const float4*)(src + 4);
    float a[8] = {v0.x, v0.y, v0.z, v0.w, v1.x, v1.y, v1.z, v1.w};

    uint4 hv, lv;
    __nv_bfloat16* hp = (__nv_bfloat16*)&hv;
    __nv_bfloat16* lp = (__nv_bfloat16*)&lv;
    #pragma unroll
    for (int j = 0; j < 8; j++) {
        hp[j] = __float2bfloat16(a[j]);
        lp[j] = __float2bfloat16(a[j] - __bfloat162float(hp[j]));
    }
    int r = t & 127;
    size_t off = ((size_t)(t >> 7) * 32 + ks) * A_BLK
               + (size_t)r * 64 + ((c ^ ((r >> 1) & 3)) << 4);
    *(uint4*)(g_a + off)        = hv;
    *(uint4*)(g_a + off + 8192) = lv;
}

__global__ __launch_bounds__(256) void convert_b_kernel(const float* __restrict__ W)
{
    int id = blockIdx.x * 256 + threadIdx.x;      // (n, ks, c)
    int c  = id & 3;
    int ks = (id >> 2) & 31;
    int n  = id >> 7;
    const float* src = W + (size_t)n * HSZ + ks * 32 + c * 8;
    float4 v0 = *(const float4*)src;
    float4 v1 = *(const float4*)(src + 4);
    float a[8] = {v0.x, v0.y, v0.z, v0.w, v1.x, v1.y, v1.z, v1.w};

    uint4 hv, lv;
    __nv_bfloat16* hp = (__nv_bfloat16*)&hv;
    __nv_bfloat16* lp = (__nv_bfloat16*)&lv;
    #pragma unroll
    for (int j = 0; j < 8; j++) {
        hp[j] = __float2bfloat16(a[j]);
        lp[j] = __float2bfloat16(a[j] - __bfloat162float(hp[j]));
    }
    int r = n & 255;
    size_t off = ((size_t)(n >> 8) * 32 + ks) * B_BLK
               + (size_t)r * 64 + ((c ^ ((r >> 1) & 3)) << 4);
    *(uint4*)(g_b + off)         = hv;
    *(uint4*)(g_b + off + 16384) = lv;
}

// ---------------------------------------------------------------------------
// Kernel A: fused scores GEMM, bf16x3 split precision on mma.sync HMMA.
// N-split: each tile's 4 n-chunks are split across 2 CTAs (2 chunks each);
// scores are additive over n, so each CTA emits a partial score vector.
// 1024 CTAs x 64 stages fixes the 512/148 wave-quantization waste (4 waves
// of 128-stage CTAs -> 7 waves of 64-stage CTAs: busiest SM 512 -> 448).
// Feeds via cp.async.bulk into a 4-deep smem ring; mbarrier complete_tx.
// ---------------------------------------------------------------------------
__global__ void __launch_bounds__(512, 1) gemm_scores_kernel(
    const float* __restrict__ bias, const float* __restrict__ key)
{
    extern __shared__ char smem[];
    const uint32_t sbase = s2u(smem);
    const int tid = threadIdx.x;
    const int wid = tid >> 5;
    const int lid = tid & 31;
    const int wm  = wid & 3;          // warp m index (4)
    const int wn  = wid >> 2;         // warp n index (4)
    const int tile = blockIdx.x >> 1;
    const int half = blockIdx.x & 1;  // n-chunk pair: {0,1} or {2,3}
    const int t0  = tile * M_CTA;

    float* s_score = (float*)(smem + SOFF_SCORE);
    float* s_key   = (float*)(smem + SOFF_KEY);
    float* s_bias  = (float*)(smem + SOFF_BIAS);
    for (int i = tid; i < HSZ; i += 512) {
        s_key[i]  = key[i];
        s_bias[i] = bias[i];
    }
    if (tid < M_CTA) s_score[tid] = 0.0f;
    if (tid == 0) {
        #pragma unroll
        for (int i = 0; i < NBUF; i++) mbar_init(sbase + SOFF_MBAR + i * 8, 1);
    }
    __syncthreads();

    // prologue: stages 0..2
    if (tid == 0) {
        #pragma unroll
        for (int s = 0; s < NBUF - 1; s++) {
            uint32_t mb = sbase + SOFF_MBAR + s * 8;
            mbar_expect_tx(mb, STAGE_BYTES);
            bulk_g2s(sbase + SOFF_STAGE + s * STAGE_BYTES,
                     g_a + ((size_t)tile * 32 + (s & 31)) * A_BLK, A_BLK, mb);
            bulk_g2s(sbase + SOFF_STAGE + s * STAGE_BYTES + STG_B,
                     g_b + ((size_t)(half * 2 + (s >> 5)) * 32 + (s & 31)) * B_BLK,
                     B_BLK, mb);
        }
    }

    // ldmatrix lane geometry
    const int g  = lid >> 3;          // quad-group 0..3
    const int r8 = lid & 7;
    const int a_row  = wm * 32 + (g & 1) * 8 + r8;   // + i*16
    const int a_kh   = g >> 1;                       // k8-half
    const int b_rowb = wn * 64 + (g >> 1) * 8 + r8;  // + nh*32 + p*16
    const int b_kh   = g & 1;
    const int a_xm   = (a_row  >> 1) & 3;            // xor mask (invariant to +16/+32)
    const int b_xm   = (b_rowb >> 1) & 3;

    float acc[2][8][4];
    float score_p[2][2];

    for (int gs = 0; gs < NSTAGES_CTA; gs++) {
        const int ks = gs & 31;
        const uint32_t stg = sbase + SOFF_STAGE + (uint32_t)(gs & 3) * STAGE_BYTES;

        if (ks == 0) {
            #pragma unroll
            for (int i = 0; i < 2; i++)
                #pragma unroll
                for (int j = 0; j < 8; j++)
                    #pragma unroll
                    for (int c = 0; c < 4; c++) acc[i][j][c] = 0.0f;
        }

        mbar_wait(sbase + SOFF_MBAR + (gs & 3) * 8, (gs >> 2) & 1);

        // issue stage gs+3 into the buffer freed at stage gs-1
        if (tid == 0 && gs + 3 < NSTAGES_CTA) {
            const int s = gs + 3;
            uint32_t mb = sbase + SOFF_MBAR + (s & 3) * 8;
            mbar_expect_tx(mb, STAGE_BYTES);
            bulk_g2s(sbase + SOFF_STAGE + (uint32_t)(s & 3) * STAGE_BYTES,
                     g_a + ((size_t)tile * 32 + (s & 31)) * A_BLK, A_BLK, mb);
            bulk_g2s(sbase + SOFF_STAGE + (uint32_t)(s & 3) * STAGE_BYTES + STG_B,
                     g_b + ((size_t)(half * 2 + (s >> 5)) * 32 + (s & 31)) * B_BLK,
                     B_BLK, mb);
        }

        #pragma unroll
        for (int k16 = 0; k16 < 2; k16++) {
            uint32_t ah[2][4], al[2][4];
            const uint32_t a_csw = (uint32_t)(((k16 * 2 + a_kh) ^ a_xm) << 4);
            #pragma unroll
            for (int i = 0; i < 2; i++) {
                uint32_t off = (uint32_t)((a_row + i * 16) << 6) + a_csw;
                LDMX4(ah[i][0], ah[i][1], ah[i][2], ah[i][3], stg + STG_AHI + off);
                LDMX4(al[i][0], al[i][1], al[i][2], al[i][3], stg + STG_ALO + off);
            }
            const uint32_t b_csw = (uint32_t)(((k16 * 2 + b_kh) ^ b_xm) << 4);
            #pragma unroll
            for (int nh = 0; nh < 2; nh++) {
                uint32_t bh[4][2], bl[4][2];
                #pragma unroll
                for (int p = 0; p < 2; p++) {
                    uint32_t off = (uint32_t)((b_rowb + nh * 32 + p * 16) << 6) + b_csw;
                    LDMX4(bh[2*p][0], bh[2*p][1], bh[2*p+1][0], bh[2*p+1][1],
                          stg + STG_B + off);
                    LDMX4(bl[2*p][0], bl[2*p][1], bl[2*p+1][0], bl[2*p+1][1],
                          stg + STG_B + 16384 + off);
                }
                #pragma unroll
                for (int i = 0; i < 2; i++)
                    #pragma unroll
                    for (int j = 0; j < 4; j++) {
                        MMA16816(acc[i][nh * 4 + j], ah[i], bh[j]);  // hi*hi
                        MMA16816(acc[i][nh * 4 + j], ah[i], bl[j]);  // hi*lo
                        MMA16816(acc[i][nh * 4 + j], al[i], bh[j]);  // lo*hi
                    }
            }
        }

        if (ks == 31) {
            // epilogue for this n-chunk: tanh(acc+bias)*key -> score partials
            const int n0 = (half * 2 + (gs >> 5)) * N_CHUNK;
            #pragma unroll
            for (int i = 0; i < 2; i++)
                #pragma unroll
                for (int mh = 0; mh < 2; mh++) score_p[i][mh] = 0.0f;

            #pragma unroll
            for (int i = 0; i < 2; i++)
                #pragma unroll
                for (int j = 0; j < 8; j++)
                    #pragma unroll
                    for (int c = 0; c < 4; c++) {
                        int n = n0 + wn * 64 + j * 8 + (lid & 3) * 2 + (c & 1);
                        float v = ftanh(acc[i][j][c] + s_bias[n]) * s_key[n];
                        score_p[i][c >> 1] += v;
                    }

            #pragma unroll
            for (int i = 0; i < 2; i++)
                #pragma unroll
                for (int mh = 0; mh < 2; mh++) {
                    float v = score_p[i][mh];
                    v += __shfl_xor_sync(0xffffffffu, v, 1);
                    v += __shfl_xor_sync(0xffffffffu, v, 2);
                    if ((lid & 3) == 0) {
                        int m = wm * 32 + i * 16 + mh * 8 + (lid >> 2);
                        atomicAdd(&s_score[m], v);
                    }
                }
        }

        __syncthreads();   // all warps done with this buffer -> reusable
    }

    if (tid < M_CTA) g_scores_part[half * NTOK + t0 + tid] = s_score[tid];
}

// ---------------------------------------------------------------------------
// Kernel B1: per-batch masked softmax over summed partial scores -> probs.
// ---------------------------------------------------------------------------
__global__ __launch_bounds__(256) void softmax_kernel(const int* __restrict__ lengths)
{
    __shared__ float red[256];
    const int b = blockIdx.x;
    const int len = lengths[b];
    const float* sc0 = g_scores_part + b * SSZ;
    const float* sc1 = g_scores_part + NTOK + b * SSZ;
    const int tid = threadIdx.x;

    float m = -1e30f;
    for (int s = tid; s < len; s += 256) m = fmaxf(m, sc0[s] + sc1[s]);
    red[tid] = m;
    __syncthreads();
    for (int o = 128; o > 0; o >>= 1) {
        if (tid < o) red[tid] = fmaxf(red[tid], red[tid + o]);
        __syncthreads();
    }
    m = red[0];
    __syncthreads();

    float sum = 0.f;
    for (int s = tid; s < len; s += 256) sum += expf(sc0[s] + sc1[s] - m);
    red[tid] = sum;
    __syncthreads();
    for (int o = 128; o > 0; o >>= 1) {
        if (tid < o) red[tid] += red[tid + o];
        __syncthreads();
    }
    const float inv = 1.0f / red[0];

    for (int s = tid; s < SSZ; s += 256)
        g_probs[b * SSZ + s] = (s < len) ? expf(sc0[s] + sc1[s] - m) * inv : 0.f;
}

// ---------------------------------------------------------------------------
// Kernel B2: out[b,h] = sum_{s<len} probs[b,s] * x[b,s,h]
// ---------------------------------------------------------------------------
__global__ __launch_bounds__(128) void output_kernel(
    const float* __restrict__ x, const int* __restrict__ lengths,
    float* __restrict__ out)
{
    const int b = blockIdx.y;
    const int h = blockIdx.x * 128 + threadIdx.x;
    const int len = lengths[b];
    const float* xb = x + (size_t)b * SSZ * HSZ + h;
    const float* pb = g_probs + b * SSZ;

    float a0 = 0.f, a1 = 0.f, a2 = 0.f, a3 = 0.f;
    int s = 0;
    for (; s + 4 <= len; s += 4) {
        a0 += pb[s + 0] * xb[(size_t)(s + 0) * HSZ];
        a1 += pb[s + 1] * xb[(size_t)(s + 1) * HSZ];
        a2 += pb[s + 2] * xb[(size_t)(s + 2) * HSZ];
        a3 += pb[s + 3] * xb[(size_t)(s + 3) * HSZ];
    }
    for (; s < len; s++) a0 += pb[s] * xb[(size_t)s * HSZ];

    out[b * HSZ + h] = (a0 + a1) + (a2 + a3);
}

// ---------------------------------------------------------------------------
extern "C" void kernel_launch(void* const* d_in, const int* in_sizes, int n_in,
                              void* d_out, int out_size)
{
    const float* x       = (const float*)d_in[0];
    const int*   lengths = (const int*)  d_in[1];
    const float* W       = (const float*)d_in[2];
    const float* bias    = (const float*)d_in[3];
    const float* key     = (const float*)d_in[4];
    float* out = (float*)d_out;

    cudaFuncSetAttribute(gemm_scores_kernel,
                         cudaFuncAttributeMaxDynamicSharedMemorySize, SMEM_TOTAL);

    convert_a_kernel<<<(NTOK * 32 * 4) / 256, 256>>>(x);
    convert_b_kernel<<<(HSZ * 32 * 4) / 256, 256>>>(W);

    gemm_scores_kernel<<<(NTOK / M_CTA) * NSPLIT, 512, SMEM_TOTAL>>>(bias, key);
    softmax_kernel<<<BSZ, 256>>>(lengths);
    output_kernel<<<dim3(HSZ / 128, BSZ), 128>>>(x, lengths, out);
}